// round 6
// baseline (speedup 1.0000x reference)
#include <cuda_runtime.h>
#include <cuda_bf16.h>
#include <cstdint>

#define N_NODES 8192
#define IN_CH   256
#define F_OUT   64
#define KSPLIT  4

// ---------------- scratch (no allocations allowed) ----------------
__device__ float g_seq[N_NODES * F_OUT];          // seq_fts fp32
__device__ float g_f1[N_NODES];
__device__ float g_f2[N_NODES];
__device__ float g_d[N_NODES];                    // column softmax denominators
__device__ __nv_bfloat16 g_ght[F_OUT * N_NODES];  // (seq_fts/d)^T hi, [n][j]
__device__ __nv_bfloat16 g_glt[F_OUT * N_NODES];  // residual lo
__device__ float g_part[KSPLIT * N_NODES * F_OUT];// K-split partial results

__device__ __forceinline__ float lrelu(float v) { return v > 0.f ? v : 0.01f * v; }
__device__ __forceinline__ uint32_t swz(uint32_t b) { return b ^ ((b >> 3) & 0x70); }

// ---------------- kernel A: projection + f1/f2 ----------------
__global__ void k_proj(const float* __restrict__ x, const float* __restrict__ W1,
                       const float* __restrict__ a1, const float* __restrict__ a2) {
    __shared__ float xs[IN_CH];
    __shared__ float red[4];
    int i = blockIdx.x;
    int t = threadIdx.x;  // 64 threads
    ((float4*)xs)[t] = ((const float4*)(x + (size_t)i * IN_CH))[t];
    __syncthreads();
    const float* w = W1 + t * IN_CH;
    float acc = 0.f;
#pragma unroll
    for (int c = 0; c < IN_CH; c += 4) {
        float4 wv = *(const float4*)(w + c);
        acc += xs[c] * wv.x + xs[c + 1] * wv.y + xs[c + 2] * wv.z + xs[c + 3] * wv.w;
    }
    g_seq[i * F_OUT + t] = acc;
    float v1 = acc * a1[t];
    float v2 = acc * a2[t];
#pragma unroll
    for (int o = 16; o > 0; o >>= 1) {
        v1 += __shfl_down_sync(0xffffffffu, v1, o);
        v2 += __shfl_down_sync(0xffffffffu, v2, o);
    }
    if ((t & 31) == 0) { red[t >> 5] = v1; red[2 + (t >> 5)] = v2; }
    __syncthreads();
    if (t == 0) { g_f1[i] = red[0] + red[1]; g_f2[i] = red[2] + red[3]; }
}

__global__ void k_initd() { g_d[blockIdx.x * 1024 + threadIdx.x] = 0.f; }

// ---------------- kernel B: column denominators (pass 1 over bias) ----------------
__global__ __launch_bounds__(256) void k_colsum(const float* __restrict__ bias) {
    __shared__ float f2s[128];
    int tid = threadIdx.x;
    int j = blockIdx.x * 1024 + tid * 4;
    int i0 = blockIdx.y * 128;
    if (tid < 128) f2s[tid] = g_f2[i0 + tid];
    __syncthreads();
    float4 f1v = *(const float4*)(g_f1 + j);
    float s0 = 0.f, s1 = 0.f, s2 = 0.f, s3 = 0.f;
    const float* bp = bias + (size_t)i0 * N_NODES + j;
#pragma unroll 4
    for (int r = 0; r < 128; r++) {
        float f2 = f2s[r];
        float4 b = *(const float4*)bp;
        bp += N_NODES;
        s0 += __expf(lrelu(f1v.x + f2) + b.x);
        s1 += __expf(lrelu(f1v.y + f2) + b.y);
        s2 += __expf(lrelu(f1v.z + f2) + b.z);
        s3 += __expf(lrelu(f1v.w + f2) + b.w);
    }
    atomicAdd(&g_d[j + 0], s0);
    atomicAdd(&g_d[j + 1], s1);
    atomicAdd(&g_d[j + 2], s2);
    atomicAdd(&g_d[j + 3], s3);
}

// ---------------- kernel C: G = seq_fts/d, transposed + bf16-split ----------------
__global__ void k_prep() {
    int idx = blockIdx.x * 256 + threadIdx.x;   // 0 .. 524287
    int n = idx >> 13;
    int j = idx & (N_NODES - 1);
    float g = g_seq[j * F_OUT + n] / g_d[j];
    __nv_bfloat16 gh = __float2bfloat16(g);
    float gl = g - __bfloat162float(gh);
    g_ght[n * N_NODES + j] = gh;
    g_glt[n * N_NODES + j] = __float2bfloat16(gl);
}

// ---------------- mma helpers ----------------
__device__ __forceinline__ void ldsm4(uint32_t (&r)[4], uint32_t addr) {
    asm volatile("ldmatrix.sync.aligned.m8n8.x4.shared.b16 {%0,%1,%2,%3}, [%4];"
                 : "=r"(r[0]), "=r"(r[1]), "=r"(r[2]), "=r"(r[3]) : "r"(addr));
}
__device__ __forceinline__ void mma16816(float (&c)[4], const uint32_t (&a)[4],
                                         uint32_t b0, uint32_t b1) {
    asm volatile(
        "mma.sync.aligned.m16n8k16.row.col.f32.bf16.bf16.f32 "
        "{%0,%1,%2,%3},{%4,%5,%6,%7},{%8,%9},{%0,%1,%2,%3};"
        : "+f"(c[0]), "+f"(c[1]), "+f"(c[2]), "+f"(c[3])
        : "r"(a[0]), "r"(a[1]), "r"(a[2]), "r"(a[3]), "r"(b0), "r"(b1));
}

// ---------------- kernel D: fused exp + split-bf16 GEMM (pass 2 over bias) ------
// ret[i,k] = sum_j exp(z_ij) * G[j,k];  E = Eh+El, G = Gh+Gl (bf16 splits)
// block: 256 thr (8 warps x 16 rows), M_TILE=128, K chunk=64, grid (64, KSPLIT)
__global__ __launch_bounds__(256, 1) void k_gemm(const float* __restrict__ bias) {
    extern __shared__ char sm[];
    const uint32_t EH = 0, EL = 16384, GH = 32768, GL = 40960;
    uint32_t sb = (uint32_t)__cvta_generic_to_shared(sm);
    int tid = threadIdx.x;
    int lane = tid & 31, warp = tid >> 5;

    // producer coordinates: each thread owns one row (pr) x 32 cols (half ph)
    int pr = tid >> 1;
    int ph = tid & 1;
    int ig = blockIdx.x * 128 + pr;
    float f2 = g_f2[ig];
    const float* brow = bias + (size_t)ig * N_NODES;

    // consumer coordinates
    int m0 = warp * 16;
    uint32_t baseA = (uint32_t)((m0 + (lane & 15)) * 128 + ((lane & 16) ? 16 : 0));
    int rB = (lane & 7) + ((lane & 16) ? 8 : 0);
    uint32_t cbB = (lane & 8) ? 16u : 0u;

    float acc[8][4];
#pragma unroll
    for (int u = 0; u < 8; u++)
#pragma unroll
        for (int v = 0; v < 4; v++) acc[u][v] = 0.f;

    int kbase = blockIdx.y * (N_NODES / KSPLIT);
    for (int ch = 0; ch < (N_NODES / KSPLIT) / 64; ch++) {
        int j0 = kbase + ch * 64;
        // ---- produce E tiles (exp + bf16 hi/lo split) ----
#pragma unroll
        for (int q = 0; q < 8; q++) {
            int c = ph * 32 + q * 4;
            float4 b4 = *(const float4*)(brow + j0 + c);
            float4 f1v = *(const float4*)(g_f1 + j0 + c);
            float e0 = __expf(lrelu(f1v.x + f2) + b4.x);
            float e1 = __expf(lrelu(f1v.y + f2) + b4.y);
            float e2 = __expf(lrelu(f1v.z + f2) + b4.z);
            float e3 = __expf(lrelu(f1v.w + f2) + b4.w);
            __nv_bfloat16 h0 = __float2bfloat16(e0), h1 = __float2bfloat16(e1);
            __nv_bfloat16 h2 = __float2bfloat16(e2), h3 = __float2bfloat16(e3);
            float l0 = e0 - __bfloat162float(h0), l1 = e1 - __bfloat162float(h1);
            float l2 = e2 - __bfloat162float(h2), l3 = e3 - __bfloat162float(h3);
            uint32_t ph01 = (uint32_t)__bfloat16_as_ushort(h0) |
                            ((uint32_t)__bfloat16_as_ushort(h1) << 16);
            uint32_t ph23 = (uint32_t)__bfloat16_as_ushort(h2) |
                            ((uint32_t)__bfloat16_as_ushort(h3) << 16);
            __nv_bfloat16 g0 = __float2bfloat16(l0), g1 = __float2bfloat16(l1);
            __nv_bfloat16 g2 = __float2bfloat16(l2), g3 = __float2bfloat16(l3);
            uint32_t pl01 = (uint32_t)__bfloat16_as_ushort(g0) |
                            ((uint32_t)__bfloat16_as_ushort(g1) << 16);
            uint32_t pl23 = (uint32_t)__bfloat16_as_ushort(g2) |
                            ((uint32_t)__bfloat16_as_ushort(g3) << 16);
            uint32_t byte = swz((uint32_t)(pr * 128 + c * 2));
            *(uint2*)(sm + EH + byte) = make_uint2(ph01, ph23);
            *(uint2*)(sm + EL + byte) = make_uint2(pl01, pl23);
        }
        // ---- produce G tiles ([n][k] transposed layout, swizzled) ----
#pragma unroll
        for (int t2 = 0; t2 < 2; t2++) {
            int t = tid + t2 * 256;
            int row = t >> 3, c16 = t & 7;
            uint4 vh = *(const uint4*)(g_ght + row * N_NODES + j0 + c16 * 8);
            uint4 vl = *(const uint4*)(g_glt + row * N_NODES + j0 + c16 * 8);
            uint32_t byte = swz((uint32_t)(row * 128 + c16 * 16));
            *(uint4*)(sm + GH + byte) = vh;
            *(uint4*)(sm + GL + byte) = vl;
        }
        __syncthreads();
        // ---- consume: 3-product split GEMM ----
#pragma unroll
        for (int s = 0; s < 4; s++) {
            uint32_t ah[4], al[4];
            uint32_t offA = swz(baseA + s * 32);
            ldsm4(ah, sb + EH + offA);
            ldsm4(al, sb + EL + offA);
#pragma unroll
            for (int nb = 0; nb < 4; nb++) {
                uint32_t gh[4], gl[4];
                uint32_t offB = swz((uint32_t)((nb * 16 + rB) * 128 + cbB + s * 32));
                ldsm4(gh, sb + GH + offB);
                ldsm4(gl, sb + GL + offB);
                mma16816(acc[2 * nb + 0], ah, gh[0], gh[1]);
                mma16816(acc[2 * nb + 1], ah, gh[2], gh[3]);
                mma16816(acc[2 * nb + 0], al, gh[0], gh[1]);
                mma16816(acc[2 * nb + 1], al, gh[2], gh[3]);
                mma16816(acc[2 * nb + 0], ah, gl[0], gl[1]);
                mma16816(acc[2 * nb + 1], ah, gl[2], gl[3]);
            }
        }
        __syncthreads();
    }
    // epilogue: write K-split partial tile
    float* dst = g_part + (size_t)blockIdx.y * (N_NODES * F_OUT);
    int row0 = blockIdx.x * 128 + m0 + (lane >> 2);
#pragma unroll
    for (int nc = 0; nc < 8; nc++) {
        int col = nc * 8 + (lane & 3) * 2;
        *(float2*)(dst + row0 * F_OUT + col) = make_float2(acc[nc][0], acc[nc][1]);
        *(float2*)(dst + (row0 + 8) * F_OUT + col) = make_float2(acc[nc][2], acc[nc][3]);
    }
}

// ---------------- kernel E: combine K-splits + ELU ----------------
__global__ void k_finish(float* __restrict__ out) {
    int idx = blockIdx.x * 256 + threadIdx.x;
    float s = g_part[idx] + g_part[idx + N_NODES * F_OUT] +
              g_part[idx + 2 * N_NODES * F_OUT] + g_part[idx + 3 * N_NODES * F_OUT];
    out[idx] = s > 0.f ? s : expm1f(s);
}

extern "C" void kernel_launch(void* const* d_in, const int* in_sizes, int n_in,
                              void* d_out, int out_size) {
    const float* x    = (const float*)d_in[0];
    const float* bias = (const float*)d_in[1];
    const float* W1   = (const float*)d_in[2];
    const float* a1   = (const float*)d_in[3];
    const float* a2   = (const float*)d_in[4];
    float* out = (float*)d_out;

    cudaFuncSetAttribute(k_gemm, cudaFuncAttributeMaxDynamicSharedMemorySize, 49152);

    k_proj<<<N_NODES, 64>>>(x, W1, a1, a2);
    k_initd<<<N_NODES / 1024, 1024>>>();
    k_colsum<<<dim3(N_NODES / 1024, 64), 256>>>(bias);
    k_prep<<<(N_NODES * F_OUT) / 256, 256>>>();
    k_gemm<<<dim3(N_NODES / 128, KSPLIT), 256, 49152>>>(bias);
    k_finish<<<(N_NODES * F_OUT) / 256, 256>>>(out);
}

// round 7
// speedup vs baseline: 1.0417x; 1.0417x over previous
#include <cuda_runtime.h>
#include <cuda_bf16.h>
#include <cstdint>

#define N_NODES 8192
#define IN_CH   256
#define F_OUT   64
#define KSPLIT  8

// ---------------- scratch (no allocations allowed) ----------------
__device__ float g_seq[N_NODES * F_OUT];          // seq_fts fp32
__device__ float g_f1[N_NODES];
__device__ float g_f2[N_NODES];
__device__ float g_d[N_NODES];                    // column softmax denominators
__device__ __nv_bfloat16 g_ght[F_OUT * N_NODES];  // (seq_fts/d)^T hi, [n][j]
__device__ __nv_bfloat16 g_glt[F_OUT * N_NODES];  // residual lo
__device__ float g_part[KSPLIT * N_NODES * F_OUT];// K-split partial results

__device__ __forceinline__ float lrelu(float v) { return v > 0.f ? v : 0.01f * v; }
__device__ __forceinline__ uint32_t swz(uint32_t b) { return b ^ ((b >> 3) & 0x70); }

// ---------------- packed f32x2 helpers (sm_103a FFMA2 path) ----------------
#define PADD2(d,a,b)   asm("add.rn.f32x2 %0,%1,%2;":"=l"(d):"l"(a),"l"(b))
#define PMUL2(d,a,b)   asm("mul.rn.f32x2 %0,%1,%2;":"=l"(d):"l"(a),"l"(b))
#define PFMA2(d,a,b,c) asm("fma.rn.f32x2 %0,%1,%2,%3;":"=l"(d):"l"(a),"l"(b),"l"(c))

__device__ __forceinline__ uint64_t dup2(float v) {
    uint64_t r; asm("mov.b64 %0,{%1,%1};" : "=l"(r) : "f"(v)); return r;
}
__device__ __forceinline__ uint64_t pk2(float lo, float hi) {
    uint64_t r; asm("mov.b64 %0,{%1,%2};" : "=l"(r) : "f"(lo), "f"(hi)); return r;
}
__device__ __forceinline__ void unpk(uint64_t v, float& lo, float& hi) {
    asm("mov.b64 {%0,%1},%2;" : "=f"(lo), "=f"(hi) : "l"(v));
}

struct EC {
    uint64_t L2E, MAG, NMAG, N1, C5, C4, C3, C2, C1, ONE, P505, P495;
};
__device__ __forceinline__ EC make_ec() {
    EC c;
    c.L2E  = dup2(1.4426950408889634f);
    c.MAG  = dup2(12583040.0f);    // 1.5*2^23 + 128  (bias k so k'>=0: no carry)
    c.NMAG = dup2(-12583040.0f);
    c.N1   = dup2(-1.0f);
    c.C5 = dup2(1.3333558e-3f);
    c.C4 = dup2(9.6181291e-3f);
    c.C3 = dup2(5.5504109e-2f);
    c.C2 = dup2(2.4022651e-1f);
    c.C1 = dup2(6.9314718e-1f);
    c.ONE = dup2(1.0f);
    c.P505 = dup2(0.505f);
    c.P495 = dup2(0.495f);
    return c;
}

// exp(lrelu(f1+f2) + b) on 2 packed fp32 lanes, entirely on fma/alu pipes.
// lrelu(s) = 0.505*s + 0.495*|s|.  exp(z) = 2^(z*log2e) via magic-round + poly5,
// exponent applied with a carry-safe packed 64-bit integer add (k biased +128).
__device__ __forceinline__ uint64_t expz2(uint64_t f1p, uint64_t f2p, uint64_t b,
                                          const EC& C) {
    uint64_t s, ab, h, lr, bl, t, km, kf, f, p;
    PADD2(s, f1p, f2p);
    ab = s & 0x7FFFFFFF7FFFFFFFull;
    PMUL2(h, s, C.P505);
    PFMA2(lr, ab, C.P495, h);
    PMUL2(bl, b, C.L2E);
    PFMA2(t, lr, C.L2E, bl);           // t = z * log2(e)
    PADD2(km, t, C.MAG);               // low 9 mantissa bits of each half = round(t)+128
    PADD2(kf, km, C.NMAG);             // kf = round(t) exactly
    PFMA2(f, kf, C.N1, t);             // f = t - round(t)  in [-0.5, 0.5]
    p = C.C5;
    PFMA2(p, p, f, C.C4);
    PFMA2(p, p, f, C.C3);
    PFMA2(p, p, f, C.C2);
    PFMA2(p, p, f, C.C1);
    PFMA2(p, p, f, C.ONE);             // p = 2^f
    // scale by 2^k: per-half (k+128)<<23 added, then remove the 128 bias.
    return (p + ((km & 0x000001FF000001FFull) << 23)) - 0x4000000040000000ull;
}

// split packed fp32 pair into bf16x2 hi + bf16x2 residual-lo
__device__ __forceinline__ void split2(uint64_t e, const EC& C,
                                       uint32_t& hh, uint32_t& ll) {
    float x0, x1; unpk(e, x0, x1);
    asm("cvt.rn.bf16x2.f32 %0,%1,%2;" : "=r"(hh) : "f"(x1), "f"(x0));
    uint32_t wlo = hh << 16, whi = hh & 0xFFFF0000u;
    uint64_t w; asm("mov.b64 %0,{%1,%2};" : "=l"(w) : "r"(wlo), "r"(whi));
    uint64_t el; PFMA2(el, w, C.N1, e);
    float y0, y1; unpk(el, y0, y1);
    asm("cvt.rn.bf16x2.f32 %0,%1,%2;" : "=r"(ll) : "f"(y1), "f"(y0));
}

// ---------------- kernel A: projection + f1/f2 ----------------
__global__ void k_proj(const float* __restrict__ x, const float* __restrict__ W1,
                       const float* __restrict__ a1, const float* __restrict__ a2) {
    __shared__ float xs[IN_CH];
    __shared__ float red[4];
    int i = blockIdx.x;
    int t = threadIdx.x;  // 64 threads
    ((float4*)xs)[t] = ((const float4*)(x + (size_t)i * IN_CH))[t];
    __syncthreads();
    const float* w = W1 + t * IN_CH;
    float acc = 0.f;
#pragma unroll
    for (int c = 0; c < IN_CH; c += 4) {
        float4 wv = *(const float4*)(w + c);
        acc += xs[c] * wv.x + xs[c + 1] * wv.y + xs[c + 2] * wv.z + xs[c + 3] * wv.w;
    }
    g_seq[i * F_OUT + t] = acc;
    float v1 = acc * a1[t];
    float v2 = acc * a2[t];
#pragma unroll
    for (int o = 16; o > 0; o >>= 1) {
        v1 += __shfl_down_sync(0xffffffffu, v1, o);
        v2 += __shfl_down_sync(0xffffffffu, v2, o);
    }
    if ((t & 31) == 0) { red[t >> 5] = v1; red[2 + (t >> 5)] = v2; }
    __syncthreads();
    if (t == 0) { g_f1[i] = red[0] + red[1]; g_f2[i] = red[2] + red[3]; }
}

__global__ void k_initd() { g_d[blockIdx.x * 1024 + threadIdx.x] = 0.f; }

// ---------------- kernel B: column denominators (pass 1 over bias) ----------------
__global__ __launch_bounds__(256) void k_colsum(const float* __restrict__ bias) {
    __shared__ float f2s[128];
    int tid = threadIdx.x;
    int j = blockIdx.x * 1024 + tid * 4;
    int i0 = blockIdx.y * 128;
    if (tid < 128) f2s[tid] = g_f2[i0 + tid];
    __syncthreads();
    EC C = make_ec();
    uint64_t f1a = pk2(g_f1[j], g_f1[j + 1]);
    uint64_t f1b = pk2(g_f1[j + 2], g_f1[j + 3]);
    uint64_t acc0 = 0ull, acc1 = 0ull;   // {0.f, 0.f}
    const char* bp = (const char*)(bias + (size_t)i0 * N_NODES + j);
#pragma unroll 4
    for (int r = 0; r < 128; r++) {
        ulonglong2 b2 = *(const ulonglong2*)bp;
        bp += N_NODES * 4;
        uint64_t f2p = dup2(f2s[r]);
        uint64_t e0 = expz2(f1a, f2p, b2.x, C);
        uint64_t e1 = expz2(f1b, f2p, b2.y, C);
        PADD2(acc0, acc0, e0);
        PADD2(acc1, acc1, e1);
    }
    float a0, a1v, a2v, a3v;
    unpk(acc0, a0, a1v);
    unpk(acc1, a2v, a3v);
    atomicAdd(&g_d[j + 0], a0);
    atomicAdd(&g_d[j + 1], a1v);
    atomicAdd(&g_d[j + 2], a2v);
    atomicAdd(&g_d[j + 3], a3v);
}

// ---------------- kernel C: G = seq_fts/d, transposed + bf16-split (smem transpose) --
__global__ void k_prep() {
    __shared__ uint16_t shh[64 * 66];
    __shared__ uint16_t shl[64 * 66];
    int t = threadIdx.x;     // 256
    int j0 = blockIdx.x * 64;
#pragma unroll
    for (int rep = 0; rep < 16; rep++) {
        int lin = rep * 256 + t;
        int n = lin & 63, jl = lin >> 6;
        float g = g_seq[(j0 + jl) * F_OUT + n] / g_d[j0 + jl];
        __nv_bfloat16 gh = __float2bfloat16(g);
        float gl = g - __bfloat162float(gh);
        shh[n * 66 + jl] = __bfloat16_as_ushort(gh);
        shl[n * 66 + jl] = __bfloat16_as_ushort(__float2bfloat16(gl));
    }
    __syncthreads();
#pragma unroll
    for (int rep = 0; rep < 16; rep++) {
        int lin = rep * 256 + t;
        int jl = lin & 63, n = lin >> 6;
        g_ght[n * N_NODES + j0 + jl] = __ushort_as_bfloat16(shh[n * 66 + jl]);
        g_glt[n * N_NODES + j0 + jl] = __ushort_as_bfloat16(shl[n * 66 + jl]);
    }
}

// ---------------- mma helpers ----------------
__device__ __forceinline__ void ldsm4(uint32_t (&r)[4], uint32_t addr) {
    asm volatile("ldmatrix.sync.aligned.m8n8.x4.shared.b16 {%0,%1,%2,%3}, [%4];"
                 : "=r"(r[0]), "=r"(r[1]), "=r"(r[2]), "=r"(r[3]) : "r"(addr));
}
__device__ __forceinline__ void mma16816(float (&c)[4], const uint32_t (&a)[4],
                                         uint32_t b0, uint32_t b1) {
    asm volatile(
        "mma.sync.aligned.m16n8k16.row.col.f32.bf16.bf16.f32 "
        "{%0,%1,%2,%3},{%4,%5,%6,%7},{%8,%9},{%0,%1,%2,%3};"
        : "+f"(c[0]), "+f"(c[1]), "+f"(c[2]), "+f"(c[3])
        : "r"(a[0]), "r"(a[1]), "r"(a[2]), "r"(a[3]), "r"(b0), "r"(b1));
}

// ---------------- kernel D: fused exp + split-bf16 GEMM (pass 2 over bias) ------
// block: 256 thr (8 warps), M_TILE=128, K chunk=64, grid (64, KSPLIT)
__global__ __launch_bounds__(256, 1) void k_gemm(const float* __restrict__ bias) {
    extern __shared__ char sm[];
    __shared__ float f2s[128];
    const uint32_t EH = 0, EL = 16384, GH = 32768, GL = 40960;
    uint32_t sb = (uint32_t)__cvta_generic_to_shared(sm);
    int tid = threadIdx.x;
    int lane = tid & 31, warp = tid >> 5;
    int i0 = blockIdx.x * 128;
    if (tid < 128) f2s[tid] = g_f2[i0 + tid];
    __syncthreads();

    EC C = make_ec();

    // consumer coordinates
    int m0 = warp * 16;
    uint32_t baseA = (uint32_t)((m0 + (lane & 15)) * 128 + ((lane & 16) ? 16 : 0));
    int rB = (lane & 7) + ((lane & 16) ? 8 : 0);
    uint32_t cbB = (lane & 8) ? 16u : 0u;

    float acc[8][4];
#pragma unroll
    for (int u = 0; u < 8; u++)
#pragma unroll
        for (int v = 0; v < 4; v++) acc[u][v] = 0.f;

    const float* bbase = bias + (size_t)i0 * N_NODES;
    int kbase = blockIdx.y * (N_NODES / KSPLIT);
    for (int ch = 0; ch < (N_NODES / KSPLIT) / 64; ch++) {
        int j0 = kbase + ch * 64;
        // ---- produce E tiles: warp covers one contiguous 256B bias row segment ----
        uint64_t f1p = *(const uint64_t*)(g_f1 + j0 + lane * 2);
#pragma unroll 4
        for (int ps = 0; ps < 16; ps++) {
            int r = ps * 8 + warp;
            uint64_t b = *(const uint64_t*)(bbase + (size_t)r * N_NODES + j0 + lane * 2);
            uint64_t f2p = dup2(f2s[r]);
            uint64_t e = expz2(f1p, f2p, b, C);
            uint32_t hh, ll;
            split2(e, C, hh, ll);
            uint32_t byte = swz((uint32_t)(r * 128 + lane * 4));
            *(uint32_t*)(sm + EH + byte) = hh;
            *(uint32_t*)(sm + EL + byte) = ll;
        }
        // ---- produce G tiles ([n][k] transposed layout, swizzled) ----
#pragma unroll
        for (int t2 = 0; t2 < 2; t2++) {
            int t = tid + t2 * 256;
            int row = t >> 3, c16 = t & 7;
            uint4 vh = *(const uint4*)(g_ght + row * N_NODES + j0 + c16 * 8);
            uint4 vl = *(const uint4*)(g_glt + row * N_NODES + j0 + c16 * 8);
            uint32_t byte = swz((uint32_t)(row * 128 + c16 * 16));
            *(uint4*)(sm + GH + byte) = vh;
            *(uint4*)(sm + GL + byte) = vl;
        }
        __syncthreads();
        // ---- consume: 3-product split GEMM ----
#pragma unroll
        for (int s = 0; s < 4; s++) {
            uint32_t ah[4], al[4];
            uint32_t offA = swz(baseA + s * 32);
            ldsm4(ah, sb + EH + offA);
            ldsm4(al, sb + EL + offA);
#pragma unroll
            for (int nb = 0; nb < 4; nb++) {
                uint32_t gh[4], gl[4];
                uint32_t offB = swz((uint32_t)((nb * 16 + rB) * 128 + cbB + s * 32));
                ldsm4(gh, sb + GH + offB);
                ldsm4(gl, sb + GL + offB);
                mma16816(acc[2 * nb + 0], ah, gh[0], gh[1]);
                mma16816(acc[2 * nb + 1], ah, gh[2], gh[3]);
                mma16816(acc[2 * nb + 0], al, gh[0], gh[1]);
                mma16816(acc[2 * nb + 1], al, gh[2], gh[3]);
                mma16816(acc[2 * nb + 0], ah, gl[0], gl[1]);
                mma16816(acc[2 * nb + 1], ah, gl[2], gl[3]);
            }
        }
        __syncthreads();
    }
    // epilogue: write K-split partial tile
    float* dst = g_part + (size_t)blockIdx.y * (N_NODES * F_OUT);
    int row0 = i0 + m0 + (lane >> 2);
#pragma unroll
    for (int nc = 0; nc < 8; nc++) {
        int col = nc * 8 + (lane & 3) * 2;
        *(float2*)(dst + row0 * F_OUT + col) = make_float2(acc[nc][0], acc[nc][1]);
        *(float2*)(dst + (row0 + 8) * F_OUT + col) = make_float2(acc[nc][2], acc[nc][3]);
    }
}

// ---------------- kernel E: combine K-splits + ELU ----------------
__global__ void k_finish(float* __restrict__ out) {
    int idx = blockIdx.x * 256 + threadIdx.x;
    float s = 0.f;
#pragma unroll
    for (int k = 0; k < KSPLIT; k++) s += g_part[idx + (size_t)k * (N_NODES * F_OUT)];
    out[idx] = s > 0.f ? s : expm1f(s);
}

extern "C" void kernel_launch(void* const* d_in, const int* in_sizes, int n_in,
                              void* d_out, int out_size) {
    const float* x    = (const float*)d_in[0];
    const float* bias = (const float*)d_in[1];
    const float* W1   = (const float*)d_in[2];
    const float* a1   = (const float*)d_in[3];
    const float* a2   = (const float*)d_in[4];
    float* out = (float*)d_out;

    cudaFuncSetAttribute(k_gemm, cudaFuncAttributeMaxDynamicSharedMemorySize, 49152);

    k_proj<<<N_NODES, 64>>>(x, W1, a1, a2);
    k_initd<<<N_NODES / 1024, 1024>>>();
    k_colsum<<<dim3(N_NODES / 1024, 64), 256>>>(bias);
    k_prep<<<N_NODES / 64, 256>>>();
    k_gemm<<<dim3(N_NODES / 128, KSPLIT), 256, 49152>>>(bias);
    k_finish<<<(N_NODES * F_OUT) / 256, 256>>>(out);
}

// round 11
// speedup vs baseline: 1.1495x; 1.1035x over previous
#include <cuda_runtime.h>
#include <cuda_fp16.h>
#include <cstdint>

#define N_NODES 8192
#define IN_CH   256
#define F_OUT   64
#define KSPLIT  4

// ---------------- scratch (no allocations allowed) ----------------
__device__ float g_seq[N_NODES * F_OUT];          // seq_fts fp32
__device__ float g_f1[N_NODES];
__device__ float g_f2[N_NODES];
__device__ float g_d[N_NODES];                    // shifted column denominators
__device__ __half g_ght[F_OUT * N_NODES];         // (seq_fts/d')^T hi fp16, [n][j]
__device__ __half g_glt[F_OUT * N_NODES];         // residual lo fp16
__device__ float g_part[KSPLIT * N_NODES * F_OUT];// K-split partial results

__device__ __forceinline__ uint32_t swz(uint32_t b) { return b ^ ((b >> 3) & 0x70); }

// ---------------- packed f32x2 helpers (sm_103a FFMA2 path) ----------------
#define PADD2(d,a,b)   asm("add.rn.f32x2 %0,%1,%2;":"=l"(d):"l"(a),"l"(b))
#define PMUL2(d,a,b)   asm("mul.rn.f32x2 %0,%1,%2;":"=l"(d):"l"(a),"l"(b))
#define PFMA2(d,a,b,c) asm("fma.rn.f32x2 %0,%1,%2,%3;":"=l"(d):"l"(a),"l"(b),"l"(c))

__device__ __forceinline__ uint64_t dup2(float v) {
    uint64_t r; asm("mov.b64 %0,{%1,%1};" : "=l"(r) : "f"(v)); return r;
}
__device__ __forceinline__ uint64_t pk2(float lo, float hi) {
    uint64_t r; asm("mov.b64 %0,{%1,%2};" : "=l"(r) : "f"(lo), "f"(hi)); return r;
}
__device__ __forceinline__ void unpk(uint64_t v, float& lo, float& hi) {
    asm("mov.b64 {%0,%1},%2;" : "=f"(lo), "=f"(hi) : "l"(v));
}

struct EC {
    uint64_t L2E, SH, MAG, NMAG, N1, C5, C4, C3, C2, C1, ONE, P505, P495;
};
__device__ __forceinline__ EC make_ec() {
    EC c;
    c.L2E  = dup2(1.4426950408889634f);
    c.SH   = dup2(-11.541560327111707f);  // -8 * log2(e)  (range shift z-8)
    c.MAG  = dup2(12583040.0f);           // 1.5*2^23 + 128
    c.NMAG = dup2(-12583040.0f);
    c.N1   = dup2(-1.0f);
    c.C5 = dup2(1.3333558e-3f);
    c.C4 = dup2(9.6181291e-3f);
    c.C3 = dup2(5.5504109e-2f);
    c.C2 = dup2(2.4022651e-1f);
    c.C1 = dup2(6.9314718e-1f);
    c.ONE = dup2(1.0f);
    c.P505 = dup2(0.505f);
    c.P495 = dup2(0.495f);
    return c;
}

// exp(lrelu(f1+f2) + b - 8) on 2 packed fp32 lanes, fma/alu pipes only.
__device__ __forceinline__ uint64_t expz2(uint64_t f1p, uint64_t f2p, uint64_t b,
                                          const EC& C) {
    uint64_t s, ab, h, lr, bl, t, km, kf, f, p;
    PADD2(s, f1p, f2p);
    ab = s & 0x7FFFFFFF7FFFFFFFull;
    PMUL2(h, s, C.P505);
    PFMA2(lr, ab, C.P495, h);            // lrelu(s)
    PFMA2(bl, b, C.L2E, C.SH);           // b*log2e - 8*log2e
    PFMA2(t, lr, C.L2E, bl);             // t = (z-8)*log2e
    PADD2(km, t, C.MAG);                 // low 9 bits/half = round(t)+128
    PADD2(kf, km, C.NMAG);               // kf = round(t) exactly
    PFMA2(f, kf, C.N1, t);               // f = t - round(t)
    p = C.C5;
    PFMA2(p, p, f, C.C4);
    PFMA2(p, p, f, C.C3);
    PFMA2(p, p, f, C.C2);
    PFMA2(p, p, f, C.C1);
    PFMA2(p, p, f, C.ONE);               // p = 2^f
    return (p + ((km & 0x000001FF000001FFull) << 23)) - 0x4000000040000000ull;
}

// ---------------- kernel A: projection + f1/f2 ----------------
__global__ void k_proj(const float* __restrict__ x, const float* __restrict__ W1,
                       const float* __restrict__ a1, const float* __restrict__ a2) {
    __shared__ float xs[IN_CH];
    __shared__ float red[4];
    int i = blockIdx.x;
    int t = threadIdx.x;  // 64 threads
    ((float4*)xs)[t] = ((const float4*)(x + (size_t)i * IN_CH))[t];
    __syncthreads();
    const float* w = W1 + t * IN_CH;
    float acc = 0.f;
#pragma unroll
    for (int c = 0; c < IN_CH; c += 4) {
        float4 wv = *(const float4*)(w + c);
        acc += xs[c] * wv.x + xs[c + 1] * wv.y + xs[c + 2] * wv.z + xs[c + 3] * wv.w;
    }
    g_seq[i * F_OUT + t] = acc;
    float v1 = acc * a1[t];
    float v2 = acc * a2[t];
#pragma unroll
    for (int o = 16; o > 0; o >>= 1) {
        v1 += __shfl_down_sync(0xffffffffu, v1, o);
        v2 += __shfl_down_sync(0xffffffffu, v2, o);
    }
    if ((t & 31) == 0) { red[t >> 5] = v1; red[2 + (t >> 5)] = v2; }
    __syncthreads();
    if (t == 0) { g_f1[i] = red[0] + red[1]; g_f2[i] = red[2] + red[3]; }
}

__global__ void k_initd() { g_d[blockIdx.x * 1024 + threadIdx.x] = 0.f; }

// ---------------- kernel B: shifted column denominators (pass 1) ----------------
__global__ __launch_bounds__(256) void k_colsum(const float* __restrict__ bias) {
    __shared__ float f2s[128];
    int tid = threadIdx.x;
    int j = blockIdx.x * 1024 + tid * 4;
    int i0 = blockIdx.y * 128;
    if (tid < 128) f2s[tid] = g_f2[i0 + tid];
    __syncthreads();
    EC C = make_ec();
    uint64_t f1a = pk2(g_f1[j], g_f1[j + 1]);
    uint64_t f1b = pk2(g_f1[j + 2], g_f1[j + 3]);
    uint64_t acc0 = 0ull, acc1 = 0ull;
    const char* bp = (const char*)(bias + (size_t)i0 * N_NODES + j);
#pragma unroll 4
    for (int r = 0; r < 128; r++) {
        ulonglong2 b2 = *(const ulonglong2*)bp;
        bp += N_NODES * 4;
        uint64_t f2p = dup2(f2s[r]);
        uint64_t e0 = expz2(f1a, f2p, b2.x, C);
        uint64_t e1 = expz2(f1b, f2p, b2.y, C);
        PADD2(acc0, acc0, e0);
        PADD2(acc1, acc1, e1);
    }
    float a0, a1v, a2v, a3v;
    unpk(acc0, a0, a1v);
    unpk(acc1, a2v, a3v);
    atomicAdd(&g_d[j + 0], a0);
    atomicAdd(&g_d[j + 1], a1v);
    atomicAdd(&g_d[j + 2], a2v);
    atomicAdd(&g_d[j + 3], a3v);
}

// ---------------- kernel C: G = seq_fts/d', transposed + fp16 hi/lo split ---------
__global__ void k_prep() {
    int idx = blockIdx.x * 256 + threadIdx.x;   // 0 .. 524287
    int n = idx >> 13;
    int j = idx & (N_NODES - 1);
    float g = g_seq[j * F_OUT + n] / g_d[j];
    __half gh = __float2half_rn(g);
    float gl = g - __half2float(gh);
    g_ght[n * N_NODES + j] = gh;
    g_glt[n * N_NODES + j] = __float2half_rn(gl);
}

// ---------------- mma helpers (fp16 in, fp32 accum) ----------------
__device__ __forceinline__ void ldsm4(uint32_t (&r)[4], uint32_t addr) {
    asm volatile("ldmatrix.sync.aligned.m8n8.x4.shared.b16 {%0,%1,%2,%3}, [%4];"
                 : "=r"(r[0]), "=r"(r[1]), "=r"(r[2]), "=r"(r[3]) : "r"(addr));
}
__device__ __forceinline__ void mma16816h(float (&c)[4], const uint32_t (&a)[4],
                                          uint32_t b0, uint32_t b1) {
    asm volatile(
        "mma.sync.aligned.m16n8k16.row.col.f32.f16.f16.f32 "
        "{%0,%1,%2,%3},{%4,%5,%6,%7},{%8,%9},{%0,%1,%2,%3};"
        : "+f"(c[0]), "+f"(c[1]), "+f"(c[2]), "+f"(c[3])
        : "r"(a[0]), "r"(a[1]), "r"(a[2]), "r"(a[3]), "r"(b0), "r"(b1));
}

// ---------------- kernel D: fused exp + 2-product fp16 GEMM, pipelined ----------
// ret[i,k] = sum_j E'[i,j] * (Gh+Gl)[j,k].  E single fp16, G split fp16.
// block: 256 thr (8 warps), M_TILE=128, K chunk=64, double-buffered smem,
// grid (64, KSPLIT).
__global__ __launch_bounds__(256) void k_gemm(const float* __restrict__ bias) {
    extern __shared__ char sm[];
    __shared__ float f2s[128];
    const uint32_t Eo = 0, GHo = 16384, GLo = 24576, BUF = 32768;
    uint32_t sb = (uint32_t)__cvta_generic_to_shared(sm);
    int tid = threadIdx.x;
    int lane = tid & 31, warp = tid >> 5;
    int i0 = blockIdx.x * 128;
    if (tid < 128) f2s[tid] = g_f2[i0 + tid];
    __syncthreads();

    EC C = make_ec();

    // consumer coordinates
    int m0 = warp * 16;
    uint32_t baseA = (uint32_t)((m0 + (lane & 15)) * 128 + ((lane & 16) ? 16 : 0));
    int rB = (lane & 7) + ((lane & 16) ? 8 : 0);
    uint32_t cbB = (lane & 8) ? 16u : 0u;

    float acc[8][4];
#pragma unroll
    for (int u = 0; u < 8; u++)
#pragma unroll
        for (int v = 0; v < 4; v++) acc[u][v] = 0.f;

    const float* bbase = bias + (size_t)i0 * N_NODES;
    int kbase = blockIdx.y * (N_NODES / KSPLIT);
    // producer G-copy coordinates: each thread owns 2x16B segments of one row
    int grow = tid >> 2, gseg = tid & 3;

    auto produce = [&](int ch) {
        int j0 = kbase + ch * 64;
        char* bufp = sm + (size_t)(ch & 1) * BUF;
        uint64_t f1p = *(const uint64_t*)(g_f1 + j0 + lane * 2);
#pragma unroll 4
        for (int ps = 0; ps < 16; ps++) {
            int r = ps * 8 + warp;
            uint64_t b = *(const uint64_t*)(bbase + (size_t)r * N_NODES + j0 + lane * 2);
            uint64_t e = expz2(f1p, dup2(f2s[r]), b, C);
            float x0, x1; unpk(e, x0, x1);
            uint32_t hh;
            asm("cvt.rn.f16x2.f32 %0,%1,%2;" : "=r"(hh) : "f"(x1), "f"(x0));
            *(uint32_t*)(bufp + Eo + swz((uint32_t)(r * 128 + lane * 4))) = hh;
        }
        // G tiles: 64 rows x 128B; 256 threads x 2 segments x 16B = 8192B (full)
#pragma unroll
        for (int h = 0; h < 2; h++) {
            int seg = gseg + h * 4;
            uint32_t gbyte = swz((uint32_t)(grow * 128 + seg * 16));
            uint4 vh = *(const uint4*)(g_ght + grow * N_NODES + j0 + seg * 8);
            uint4 vl = *(const uint4*)(g_glt + grow * N_NODES + j0 + seg * 8);
            *(uint4*)(bufp + GHo + gbyte) = vh;
            *(uint4*)(bufp + GLo + gbyte) = vl;
        }
    };
    auto consume = [&](int ch) {
        uint32_t bb = sb + (uint32_t)(ch & 1) * BUF;
#pragma unroll
        for (int s = 0; s < 4; s++) {
            uint32_t a[4];
            ldsm4(a, bb + Eo + swz(baseA + s * 32));
#pragma unroll
            for (int nb = 0; nb < 4; nb++) {
                uint32_t offB = swz((uint32_t)((nb * 16 + rB) * 128 + cbB + s * 32));
                uint32_t gh[4], gl[4];
                ldsm4(gh, bb + GHo + offB);
                ldsm4(gl, bb + GLo + offB);
                mma16816h(acc[2 * nb + 0], a, gh[0], gh[1]);
                mma16816h(acc[2 * nb + 1], a, gh[2], gh[3]);
                mma16816h(acc[2 * nb + 0], a, gl[0], gl[1]);
                mma16816h(acc[2 * nb + 1], a, gl[2], gl[3]);
            }
        }
    };

    const int NCH = (N_NODES / KSPLIT) / 64;   // 32
    produce(0);
    __syncthreads();
    for (int ch = 0; ch < NCH; ch++) {
        if (ch + 1 < NCH) produce(ch + 1);   // overlaps with consume on other buffer
        consume(ch);
        __syncthreads();
    }

    // epilogue: write K-split partial tile
    float* dst = g_part + (size_t)blockIdx.y * (N_NODES * F_OUT);
    int row0 = i0 + m0 + (lane >> 2);
#pragma unroll
    for (int nc = 0; nc < 8; nc++) {
        int col = nc * 8 + (lane & 3) * 2;
        *(float2*)(dst + row0 * F_OUT + col) = make_float2(acc[nc][0], acc[nc][1]);
        *(float2*)(dst + (row0 + 8) * F_OUT + col) = make_float2(acc[nc][2], acc[nc][3]);
    }
}

// ---------------- kernel E: combine K-splits + ELU ----------------
__global__ void k_finish(float* __restrict__ out) {
    int idx = blockIdx.x * 256 + threadIdx.x;
    float s = 0.f;
#pragma unroll
    for (int k = 0; k < KSPLIT; k++) s += g_part[idx + (size_t)k * (N_NODES * F_OUT)];
    out[idx] = s > 0.f ? s : expm1f(s);
}

extern "C" void kernel_launch(void* const* d_in, const int* in_sizes, int n_in,
                              void* d_out, int out_size) {
    const float* x    = (const float*)d_in[0];
    const float* bias = (const float*)d_in[1];
    const float* W1   = (const float*)d_in[2];
    const float* a1   = (const float*)d_in[3];
    const float* a2   = (const float*)d_in[4];
    float* out = (float*)d_out;

    cudaFuncSetAttribute(k_gemm, cudaFuncAttributeMaxDynamicSharedMemorySize, 65536);

    k_proj<<<N_NODES, 64>>>(x, W1, a1, a2);
    k_initd<<<N_NODES / 1024, 1024>>>();
    k_colsum<<<dim3(N_NODES / 1024, 64), 256>>>(bias);
    k_prep<<<(N_NODES * F_OUT) / 256, 256>>>();
    k_gemm<<<dim3(N_NODES / 128, KSPLIT), 256, 65536>>>(bias);
    k_finish<<<(N_NODES * F_OUT) / 256, 256>>>(out);
}

// round 15
// speedup vs baseline: 1.6938x; 1.4735x over previous
#include <cuda_runtime.h>
#include <cuda_fp16.h>
#include <cstdint>

#define N_NODES 8192
#define IN_CH   256
#define F_OUT   64
#define KSPLIT  4

// ---------------- scratch (no allocations allowed) ----------------
__device__ float g_seq[N_NODES * F_OUT];          // seq_fts fp32
__device__ float g_f1[N_NODES];
__device__ float g_f2[N_NODES];
__device__ float g_d[N_NODES];                    // shifted column denominators
__device__ __half g_gt[F_OUT * N_NODES];          // (seq_fts/d')^T fp16, [n][j]
__device__ __half g_E[(size_t)N_NODES * N_NODES]; // E'=exp(z-8) fp16, swizzled tiles
__device__ float g_part[KSPLIT * N_NODES * F_OUT];// K-split partial results

__device__ __forceinline__ uint32_t swz(uint32_t b) { return b ^ ((b >> 3) & 0x70); }

// ---------------- packed f32x2 helpers (sm_103a FFMA2 path) ----------------
#define PADD2(d,a,b)   asm("add.rn.f32x2 %0,%1,%2;":"=l"(d):"l"(a),"l"(b))
#define PMUL2(d,a,b)   asm("mul.rn.f32x2 %0,%1,%2;":"=l"(d):"l"(a),"l"(b))
#define PFMA2(d,a,b,c) asm("fma.rn.f32x2 %0,%1,%2,%3;":"=l"(d):"l"(a),"l"(b),"l"(c))

__device__ __forceinline__ uint64_t dup2(float v) {
    uint64_t r; asm("mov.b64 %0,{%1,%1};" : "=l"(r) : "f"(v)); return r;
}
__device__ __forceinline__ uint64_t pk2(float lo, float hi) {
    uint64_t r; asm("mov.b64 %0,{%1,%2};" : "=l"(r) : "f"(lo), "f"(hi)); return r;
}
__device__ __forceinline__ void unpk(uint64_t v, float& lo, float& hi) {
    asm("mov.b64 {%0,%1},%2;" : "=f"(lo), "=f"(hi) : "l"(v));
}

struct EC {
    uint64_t L2E, SH, MAG, NMAG, N1, C5, C4, C3, C2, C1, ONE, P505, P495;
};
__device__ __forceinline__ EC make_ec() {
    EC c;
    c.L2E  = dup2(1.4426950408889634f);
    c.SH   = dup2(-11.541560327111707f);  // -8 * log2(e)  (range shift z-8)
    c.MAG  = dup2(12583040.0f);           // 1.5*2^23 + 128
    c.NMAG = dup2(-12583040.0f);
    c.N1   = dup2(-1.0f);
    c.C5 = dup2(1.3333558e-3f);
    c.C4 = dup2(9.6181291e-3f);
    c.C3 = dup2(5.5504109e-2f);
    c.C2 = dup2(2.4022651e-1f);
    c.C1 = dup2(6.9314718e-1f);
    c.ONE = dup2(1.0f);
    c.P505 = dup2(0.505f);
    c.P495 = dup2(0.495f);
    return c;
}

// exp(lrelu(f1+f2) + b - 8) on 2 packed fp32 lanes, fma/alu pipes only.
__device__ __forceinline__ uint64_t expz2(uint64_t f1p, uint64_t f2p, uint64_t b,
                                          const EC& C) {
    uint64_t s, ab, h, lr, bl, t, km, kf, f, p;
    PADD2(s, f1p, f2p);
    ab = s & 0x7FFFFFFF7FFFFFFFull;
    PMUL2(h, s, C.P505);
    PFMA2(lr, ab, C.P495, h);            // lrelu(s)
    PFMA2(bl, b, C.L2E, C.SH);           // b*log2e - 8*log2e
    PFMA2(t, lr, C.L2E, bl);             // t = (z-8)*log2e
    PADD2(km, t, C.MAG);                 // low 9 bits/half = round(t)+128
    PADD2(kf, km, C.NMAG);               // kf = round(t) exactly
    PFMA2(f, kf, C.N1, t);               // f = t - round(t)
    p = C.C5;
    PFMA2(p, p, f, C.C4);
    PFMA2(p, p, f, C.C3);
    PFMA2(p, p, f, C.C2);
    PFMA2(p, p, f, C.C1);
    PFMA2(p, p, f, C.ONE);               // p = 2^f
    return (p + ((km & 0x000001FF000001FFull) << 23)) - 0x4000000040000000ull;
}

// ---------------- kernel A: projection + f1/f2 ----------------
__global__ void k_proj(const float* __restrict__ x, const float* __restrict__ W1,
                       const float* __restrict__ a1, const float* __restrict__ a2) {
    __shared__ float xs[IN_CH];
    __shared__ float red[4];
    int i = blockIdx.x;
    int t = threadIdx.x;  // 64 threads
    ((float4*)xs)[t] = ((const float4*)(x + (size_t)i * IN_CH))[t];
    __syncthreads();
    const float* w = W1 + t * IN_CH;
    float acc = 0.f;
#pragma unroll
    for (int c = 0; c < IN_CH; c += 4) {
        float4 wv = *(const float4*)(w + c);
        acc += xs[c] * wv.x + xs[c + 1] * wv.y + xs[c + 2] * wv.z + xs[c + 3] * wv.w;
    }
    g_seq[i * F_OUT + t] = acc;
    float v1 = acc * a1[t];
    float v2 = acc * a2[t];
#pragma unroll
    for (int o = 16; o > 0; o >>= 1) {
        v1 += __shfl_down_sync(0xffffffffu, v1, o);
        v2 += __shfl_down_sync(0xffffffffu, v2, o);
    }
    if ((t & 31) == 0) { red[t >> 5] = v1; red[2 + (t >> 5)] = v2; }
    __syncthreads();
    if (t == 0) { g_f1[i] = red[0] + red[1]; g_f2[i] = red[2] + red[3]; }
}

__global__ void k_initd() { g_d[blockIdx.x * 1024 + threadIdx.x] = 0.f; }

// ---------------- kernel B: pass 1 — E' fp16 (swizzled tiles) + column sums -------
// grid (8, 64): block covers j in [bx*1024, +1024), i in [by*128, +128).
__global__ __launch_bounds__(256) void k_pass1(const float* __restrict__ bias) {
    __shared__ float f2s[128];
    int tid = threadIdx.x;
    int jl = tid * 4;                       // j within block stripe
    int j = blockIdx.x * 1024 + jl;
    int i0 = blockIdx.y * 128;
    if (tid < 128) f2s[tid] = g_f2[i0 + tid];
    __syncthreads();
    EC C = make_ec();
    uint64_t f1a = pk2(g_f1[j], g_f1[j + 1]);
    uint64_t f1b = pk2(g_f1[j + 2], g_f1[j + 3]);
    uint64_t acc0 = 0ull, acc1 = 0ull;
    const char* bp = (const char*)(bias + (size_t)i0 * N_NODES + j);
    // E tile destination: tile (ib, jc), 16384 B each, swizzled layout
    int jc = j >> 6;
    uint32_t c2 = (uint32_t)((jl & 63) * 2);
    char* ebase = (char*)g_E + ((size_t)blockIdx.y * 128 + jc) * 16384;
#pragma unroll 4
    for (int r = 0; r < 128; r++) {
        ulonglong2 b2 = *(const ulonglong2*)bp;
        bp += N_NODES * 4;
        uint64_t f2p = dup2(f2s[r]);
        uint64_t e0 = expz2(f1a, f2p, b2.x, C);
        uint64_t e1 = expz2(f1b, f2p, b2.y, C);
        PADD2(acc0, acc0, e0);
        PADD2(acc1, acc1, e1);
        float x0, x1, x2, x3;
        unpk(e0, x0, x1);
        unpk(e1, x2, x3);
        uint32_t h01, h23;
        asm("cvt.rn.f16x2.f32 %0,%1,%2;" : "=r"(h01) : "f"(x1), "f"(x0));
        asm("cvt.rn.f16x2.f32 %0,%1,%2;" : "=r"(h23) : "f"(x3), "f"(x2));
        *(uint2*)(ebase + swz((uint32_t)(r * 128) + c2)) = make_uint2(h01, h23);
    }
    float a0, a1v, a2v, a3v;
    unpk(acc0, a0, a1v);
    unpk(acc1, a2v, a3v);
    atomicAdd(&g_d[j + 0], a0);
    atomicAdd(&g_d[j + 1], a1v);
    atomicAdd(&g_d[j + 2], a2v);
    atomicAdd(&g_d[j + 3], a3v);
}

// ---------------- kernel C: G = seq_fts/d', transposed fp16 ----------------
__global__ void k_prep() {
    int idx = blockIdx.x * 256 + threadIdx.x;   // 0 .. 524287
    int n = idx >> 13;
    int j = idx & (N_NODES - 1);
    float g = g_seq[j * F_OUT + n] / g_d[j];
    g_gt[n * N_NODES + j] = __float2half_rn(g);
}

// ---------------- mma / cp.async helpers ----------------
__device__ __forceinline__ void ldsm4(uint32_t (&r)[4], uint32_t addr) {
    asm volatile("ldmatrix.sync.aligned.m8n8.x4.shared.b16 {%0,%1,%2,%3}, [%4];"
                 : "=r"(r[0]), "=r"(r[1]), "=r"(r[2]), "=r"(r[3]) : "r"(addr));
}
__device__ __forceinline__ void mma16816h(float (&c)[4], const uint32_t (&a)[4],
                                          uint32_t b0, uint32_t b1) {
    asm volatile(
        "mma.sync.aligned.m16n8k16.row.col.f32.f16.f16.f32 "
        "{%0,%1,%2,%3},{%4,%5,%6,%7},{%8,%9},{%0,%1,%2,%3};"
        : "+f"(c[0]), "+f"(c[1]), "+f"(c[2]), "+f"(c[3])
        : "r"(a[0]), "r"(a[1]), "r"(a[2]), "r"(a[3]), "r"(b0), "r"(b1));
}
__device__ __forceinline__ void cpa16(uint32_t dst, const void* src) {
    asm volatile("cp.async.cg.shared.global [%0], [%1], 16;"
                 :: "r"(dst), "l"(src) : "memory");
}
#define CP_COMMIT() asm volatile("cp.async.commit_group;" ::: "memory")

// ---------------- kernel D: cp.async-fed single-product fp16 GEMM ----------------
// ret[i,k] = sum_j E'[i,j] * G[j,k].  E preswizzled in gmem, pure copy producer.
// block: 256 thr (8 warps), M_TILE=128, K chunk=64, double buffer, grid (64, KSPLIT)
__global__ __launch_bounds__(256) void k_gemm() {
    extern __shared__ char sm[];
    const uint32_t Eo = 0, Go = 16384, BUF = 24576;
    uint32_t sb = (uint32_t)__cvta_generic_to_shared(sm);
    int tid = threadIdx.x;
    int lane = tid & 31, warp = tid >> 5;
    int i0 = blockIdx.x * 128;

    // consumer coordinates
    int m0 = warp * 16;
    uint32_t baseA = (uint32_t)((m0 + (lane & 15)) * 128 + ((lane & 16) ? 16 : 0));
    int rB = (lane & 7) + ((lane & 16) ? 8 : 0);
    uint32_t cbB = (lane & 8) ? 16u : 0u;

    float acc[8][4];
#pragma unroll
    for (int u = 0; u < 8; u++)
#pragma unroll
        for (int v = 0; v < 4; v++) acc[u][v] = 0.f;

    int kbase = blockIdx.y * (N_NODES / KSPLIT);
    const char* etiles = (const char*)g_E + (size_t)blockIdx.x * 128 * 16384;
    int grow = tid >> 3, gseg = tid & 7;    // G copy: 256 thr x 2 x 16B = 8192B

    auto produce = [&](int ch) {
        int j0 = kbase + ch * 64;
        uint32_t bufb = sb + (uint32_t)(ch & 1) * BUF;
        const char* esrc = etiles + (size_t)(j0 >> 6) * 16384;
#pragma unroll
        for (int t = 0; t < 4; t++) {
            uint32_t off = (uint32_t)(tid * 16 + t * 4096);
            cpa16(bufb + Eo + off, esrc + off);
        }
#pragma unroll
        for (int h = 0; h < 2; h++) {
            int row = grow + h * 32;
            uint32_t gbyte = swz((uint32_t)(row * 128 + gseg * 16));
            cpa16(bufb + Go + gbyte, g_gt + row * N_NODES + j0 + gseg * 8);
        }
        CP_COMMIT();
    };
    auto consume = [&](int ch) {
        uint32_t bb = sb + (uint32_t)(ch & 1) * BUF;
#pragma unroll
        for (int s = 0; s < 4; s++) {
            uint32_t a[4];
            ldsm4(a, bb + Eo + swz(baseA + s * 32));
#pragma unroll
            for (int nb = 0; nb < 4; nb++) {
                uint32_t gh[4];
                ldsm4(gh, bb + Go + swz((uint32_t)((nb * 16 + rB) * 128 + cbB + s * 32)));
                mma16816h(acc[2 * nb + 0], a, gh[0], gh[1]);
                mma16816h(acc[2 * nb + 1], a, gh[2], gh[3]);
            }
        }
    };

    const int NCH = (N_NODES / KSPLIT) / 64;   // 32
    produce(0);
    for (int ch = 0; ch < NCH; ch++) {
        if (ch + 1 < NCH) {
            produce(ch + 1);
            asm volatile("cp.async.wait_group 1;" ::: "memory");
        } else {
            asm volatile("cp.async.wait_group 0;" ::: "memory");
        }
        __syncthreads();
        consume(ch);
        __syncthreads();
    }

    // epilogue: write K-split partial tile
    float* dst = g_part + (size_t)blockIdx.y * (N_NODES * F_OUT);
    int row0 = i0 + m0 + (lane >> 2);
#pragma unroll
    for (int nc = 0; nc < 8; nc++) {
        int col = nc * 8 + (lane & 3) * 2;
        *(float2*)(dst + row0 * F_OUT + col) = make_float2(acc[nc][0], acc[nc][1]);
        *(float2*)(dst + (row0 + 8) * F_OUT + col) = make_float2(acc[nc][2], acc[nc][3]);
    }
}

// ---------------- kernel E: combine K-splits + ELU ----------------
__global__ void k_finish(float* __restrict__ out) {
    int idx = blockIdx.x * 256 + threadIdx.x;
    float s = 0.f;
#pragma unroll
    for (int k = 0; k < KSPLIT; k++) s += g_part[idx + (size_t)k * (N_NODES * F_OUT)];
    out[idx] = s > 0.f ? s : expm1f(s);
}

extern "C" void kernel_launch(void* const* d_in, const int* in_sizes, int n_in,
                              void* d_out, int out_size) {
    const float* x    = (const float*)d_in[0];
    const float* bias = (const float*)d_in[1];
    const float* W1   = (const float*)d_in[2];
    const float* a1   = (const float*)d_in[3];
    const float* a2   = (const float*)d_in[4];
    float* out = (float*)d_out;

    cudaFuncSetAttribute(k_gemm, cudaFuncAttributeMaxDynamicSharedMemorySize, 49152);

    k_proj<<<N_NODES, 64>>>(x, W1, a1, a2);
    k_initd<<<N_NODES / 1024, 1024>>>();
    k_pass1<<<dim3(N_NODES / 1024, 64), 256>>>(bias);
    k_prep<<<(N_NODES * F_OUT) / 256, 256>>>();
    k_gemm<<<dim3(N_NODES / 128, KSPLIT), 256, 49152>>>();
    k_finish<<<(N_NODES * F_OUT) / 256, 256>>>(out);
}